// round 4
// baseline (speedup 1.0000x reference)
#include <cuda_runtime.h>

typedef unsigned long long ull;

// Problem sizes: B=128, S=64, H=256, E=256, V=16000, T=32, START=1
// Inputs (metadata order):
// 0 encoder_outputs [128,64,256] f32
// 1 enc_h [1,128,256]  2 enc_c [1,128,256]
// 3 target_tensor [128,32] i32
// 4 embedding [16000,256]
// 5 W_attn [256,256] (UNUSED: tanh(h@W_attn.T) term is constant over s -> cancels in softmax)
// 6 U_attn [256,256]  7 V_attn [1,256]
// 8 W_ih [1024,512]   9 W_hh [1024,256]
// 10 b_ih [1024]      11 b_hh [1024]
// 12 W_out [16000,256] 13 b_out [16000]
// Output: decoder_outputs [128,32,16000] ++ h [1,128,256] ++ attentions [128,32,64]

// ---------------- device scratch (no mallocs allowed) ----------------
__device__ __align__(16) float g_u[256];            // u[h] = sum_g V[g]*U[g,h]
__device__ __align__(16) float g_bsum[1024];        // b_ih + b_hh
__device__ __align__(16) float g_w[128 * 64];       // attention weights (step-invariant)
__device__ __align__(16) float g_xcat[4096 * 512];  // [(t*128+b), 512] = [emb_relu | context]
__device__ __align__(16) float g_gpre[4096 * 1024]; // xcat @ W_ih.T + bsum
__device__ __align__(16) float g_hbuf[2][128 * 256];
__device__ __align__(16) float g_cstate[128 * 256];
__device__ __align__(16) float g_Hs[4096 * 256];    // [(b*32+t), 256] hidden states

// ---------------- f32x2 helpers (PTX-only packed FMA) ----------------
__device__ __forceinline__ void ffma2(ull &c, ull a, ull b) {
    asm("fma.rn.f32x2 %0, %1, %2, %0;" : "+l"(c) : "l"(a), "l"(b));
}
__device__ __forceinline__ float2 lo_hi(ull v) {
    float2 r; asm("mov.b64 {%0, %1}, %2;" : "=f"(r.x), "=f"(r.y) : "l"(v)); return r;
}

// ---------------- init: copy initial h / c ----------------
__global__ void k_init(const float* __restrict__ eh, const float* __restrict__ ec) {
    int i = blockIdx.x * 256 + threadIdx.x;   // grid 128 -> 32768
    g_hbuf[0][i] = eh[i];
    g_cstate[i]  = ec[i];
}

// ---------------- prep: u = V @ U_attn ; bsum = b_ih + b_hh ----------------
__global__ void k_prep(const float* __restrict__ Vat, const float* __restrict__ Uat,
                       const float* __restrict__ bih, const float* __restrict__ bhh) {
    int tid = threadIdx.x;
    if (blockIdx.x == 0) {
        float a = 0.f;
        for (int g = 0; g < 256; g++) a += Vat[g] * Uat[g * 256 + tid];
        g_u[tid] = a;
    } else {
        int nn = (blockIdx.x - 1) * 256 + tid;
        g_bsum[nn] = bih[nn] + bhh[nn];
    }
}

// ---------------- embedding gather + relu into xcat[:, 0:256] ----------------
__global__ void k_embed(const int* __restrict__ tgt, const float* __restrict__ emb) {
    int r = blockIdx.x;           // t*128 + b, grid 4096
    int t = r >> 7, b = r & 127;
    int tok = (t == 0) ? 1 : tgt[b * 32 + (t - 1)];
    float v = emb[(size_t)tok * 256 + threadIdx.x];
    g_xcat[(size_t)r * 512 + threadIdx.x] = fmaxf(v, 0.f);
}

// ---------------- attention scores + softmax (step-invariant) ----------------
__global__ void k_attn(const float* __restrict__ enc, float* __restrict__ out_attn) {
    __shared__ float usm[256];
    __shared__ float sc[64];
    int b = blockIdx.x, s = threadIdx.x;    // 128 blocks x 64 threads
    for (int i = s; i < 256; i += 64) usm[i] = g_u[i];
    __syncthreads();
    const float4* row = (const float4*)(enc + ((size_t)b * 64 + s) * 256);
    float acc = 0.f;
    #pragma unroll 8
    for (int k = 0; k < 64; k++) {
        float4 e = row[k];
        acc += e.x * usm[k*4] + e.y * usm[k*4+1] + e.z * usm[k*4+2] + e.w * usm[k*4+3];
    }
    sc[s] = acc; __syncthreads();
    float m = sc[0];
    for (int i = 1; i < 64; i++) m = fmaxf(m, sc[i]);
    float e = expf(acc - m);
    __syncthreads();
    sc[s] = e; __syncthreads();
    float sum = 0.f;
    for (int i = 0; i < 64; i++) sum += sc[i];
    float w = e / sum;
    g_w[b * 64 + s] = w;
    #pragma unroll
    for (int t = 0; t < 32; t++) out_attn[(size_t)b * 2048 + t * 64 + s] = w;
}

// ---------------- context = w @ enc ; broadcast into xcat[:, 256:512] ----------------
__global__ void k_ctx(const float* __restrict__ enc) {
    __shared__ float wsh[64];
    int b = blockIdx.x, h = threadIdx.x;    // 128 blocks x 256 threads
    if (h < 64) wsh[h] = g_w[b * 64 + h];
    __syncthreads();
    float acc = 0.f;
    #pragma unroll 8
    for (int s = 0; s < 64; s++) acc += wsh[s] * enc[((size_t)b * 64 + s) * 256 + h];
    #pragma unroll
    for (int t = 0; t < 32; t++)
        g_xcat[(size_t)(t * 128 + b) * 512 + 256 + h] = acc;
}

// ---------------- SGEMM: C[M,N] = A[M,K] @ B[N,K]^T + bias ----------------
// 128x128 block tile, 8x8/thread (split 4+4 rows / 4+4 cols), BK=8 double-buffered.
// A stored in smem pre-duplicated as float2{v,v} so f32x2 a-operands load directly
// (no per-kk dup MOVs). B tiles read at 16B stride -> conflict-free LDS.128.
// MODE 0: A=g_xcat, bias=g_bsum, C=g_gpre  (K=512)
// MODE 1: A=g_Hs,   bias=arg,    C=arg     (K=256, C=d_out)
template<int MODE, int KK, int LDA, int LDB, int LDC>
__global__ __launch_bounds__(256) void sgemm(const float* __restrict__ Bmat,
                                             const float* __restrict__ bias_ext,
                                             float* __restrict__ Cext) {
    const float* A    = (MODE == 0) ? g_xcat : g_Hs;
    const float* bias = (MODE == 0) ? g_bsum : bias_ext;
    float*       C    = (MODE == 0) ? g_gpre : Cext;

    __shared__ __align__(16) float2 As[2][8][132];   // duplicated pairs
    __shared__ __align__(16) float  Bs[2][8][132];

    int m0 = blockIdx.y * 128, n0 = blockIdx.x * 128;
    int tid = threadIdx.x;
    int ra = tid >> 1, ka = (tid & 1) * 4;
    const float* Ap = A    + (size_t)(m0 + ra) * LDA + ka;
    const float* Bp = Bmat + (size_t)(n0 + ra) * LDB + ka;

    float4 av = *(const float4*)Ap;
    float4 bv = *(const float4*)Bp;
    As[0][ka+0][ra] = make_float2(av.x, av.x);
    As[0][ka+1][ra] = make_float2(av.y, av.y);
    As[0][ka+2][ra] = make_float2(av.z, av.z);
    As[0][ka+3][ra] = make_float2(av.w, av.w);
    Bs[0][ka+0][ra] = bv.x; Bs[0][ka+1][ra] = bv.y; Bs[0][ka+2][ra] = bv.z; Bs[0][ka+3][ra] = bv.w;
    __syncthreads();

    int tx = tid & 15, ty = tid >> 4;
    // rows: {ty*4+i} u {64+ty*4+i}; col pairs: {tx*4 pairs} u {64+tx*4 pairs}
    ull acc[8][4];
    #pragma unroll
    for (int i = 0; i < 8; i++)
        #pragma unroll
        for (int j = 0; j < 4; j++) acc[i][j] = 0ull;

    const int KT = KK / 8;
    #pragma unroll 1
    for (int kt = 0; kt < KT; kt++) {
        if (kt + 1 < KT) {
            av = *(const float4*)(Ap + (kt + 1) * 8);
            bv = *(const float4*)(Bp + (kt + 1) * 8);
        }
        int buf = kt & 1;
        #pragma unroll
        for (int kk = 0; kk < 8; kk++) {
            ulonglong2 a01 = *(const ulonglong2*)&As[buf][kk][ty * 4];
            ulonglong2 a23 = *(const ulonglong2*)&As[buf][kk][ty * 4 + 2];
            ulonglong2 a45 = *(const ulonglong2*)&As[buf][kk][64 + ty * 4];
            ulonglong2 a67 = *(const ulonglong2*)&As[buf][kk][64 + ty * 4 + 2];
            ulonglong2 b01 = *(const ulonglong2*)&Bs[buf][kk][tx * 4];
            ulonglong2 b23 = *(const ulonglong2*)&Bs[buf][kk][64 + tx * 4];
            ull ad[8] = {a01.x, a01.y, a23.x, a23.y, a45.x, a45.y, a67.x, a67.y};
            ull bb[4] = {b01.x, b01.y, b23.x, b23.y};
            #pragma unroll
            for (int i = 0; i < 8; i++) {
                ffma2(acc[i][0], ad[i], bb[0]);
                ffma2(acc[i][1], ad[i], bb[1]);
                ffma2(acc[i][2], ad[i], bb[2]);
                ffma2(acc[i][3], ad[i], bb[3]);
            }
        }
        if (kt + 1 < KT) {
            int nb = buf ^ 1;
            As[nb][ka+0][ra] = make_float2(av.x, av.x);
            As[nb][ka+1][ra] = make_float2(av.y, av.y);
            As[nb][ka+2][ra] = make_float2(av.z, av.z);
            As[nb][ka+3][ra] = make_float2(av.w, av.w);
            Bs[nb][ka+0][ra] = bv.x; Bs[nb][ka+1][ra] = bv.y; Bs[nb][ka+2][ra] = bv.z; Bs[nb][ka+3][ra] = bv.w;
            __syncthreads();
        }
    }

    float4 bsLo = *(const float4*)&bias[n0 + tx * 4];
    float4 bsHi = *(const float4*)&bias[n0 + 64 + tx * 4];
    #pragma unroll
    for (int i = 0; i < 8; i++) {
        int row = m0 + ((i < 4) ? (ty * 4 + i) : (64 + ty * 4 + i - 4));
        float2 p0 = lo_hi(acc[i][0]), p1 = lo_hi(acc[i][1]);
        float2 p2 = lo_hi(acc[i][2]), p3 = lo_hi(acc[i][3]);
        float4 o0 = make_float4(p0.x + bsLo.x, p0.y + bsLo.y, p1.x + bsLo.z, p1.y + bsLo.w);
        float4 o1 = make_float4(p2.x + bsHi.x, p2.y + bsHi.y, p3.x + bsHi.z, p3.y + bsHi.w);
        *(float4*)&C[(size_t)row * LDC + n0 + tx * 4]      = o0;
        *(float4*)&C[(size_t)row * LDC + n0 + 64 + tx * 4] = o1;
    }
}

// ---------------- recurrent step: gates = gpre + h@W_hh^T ; LSTM pointwise ----------------
// grid 128 = (bi 0..1) x (j 0..63). Block: 64 batch rows x 4 h-units (16 gate rows).
// Warp-partitioned batch (warp w owns local b in [w*8,w*8+8)) -> smem reads broadcast.
// h tile transposed [k][b] with XOR swizzle; W_hh rows stored as duplicated float2
// so the f32x2 w-operand is a single LDS.64 (no dup MOVs in the hot loop).
#define STEP_SMEM_FLOATS (256*64 + 256*17*2 + 16*64)
#define STEP_SMEM_BYTES  (STEP_SMEM_FLOATS * 4)

__global__ __launch_bounds__(256) void k_step(const float* __restrict__ Whh, int t, int par,
                                              float* __restrict__ hfinal) {
    extern __shared__ __align__(16) float sm[];
    float*  hsm  = sm;                              // [k 256][b 64], XOR-swizzled
    float2* Wsm2 = (float2*)(sm + 256 * 64);        // [k 256][row 16] dup pairs, stride 17
    float*  gsm  = sm + 256 * 64 + 256 * 17 * 2;    // [16][64]

    int tid = threadIdx.x;
    int j  = blockIdx.x & 63;
    int bi = blockIdx.x >> 6;

    const float* hprev = g_hbuf[par] + bi * 64 * 256;

    // load h transposed, coalesced LDG.128 + swizzled STS
    #pragma unroll
    for (int i = 0; i < 16; i++) {
        int idx = tid + i * 256;        // 0..4095
        int bl = idx >> 6;              // 0..63
        int kq = (idx & 63) << 2;       // 0,4,..252
        float4 v = *(const float4*)&hprev[bl * 256 + kq];
        float vv[4] = {v.x, v.y, v.z, v.w};
        #pragma unroll
        for (int d = 0; d < 4; d++) {
            int k = kq + d;
            int fs = ((k >> 2) & 7) << 2;
            hsm[k * 64 + (bl ^ fs)] = vv[d];
        }
    }
    // load 16 W_hh rows as duplicated float2 (stride 17 -> conflict-free LDS.64)
    #pragma unroll
    for (int i = 0; i < 16; i++) {
        int idx = tid + i * 256;        // 0..4095
        int row = idx >> 8;             // 0..15
        int k   = idx & 255;
        int hu   = j * 4 + (row & 3);
        int gate = row >> 2;
        float wv = Whh[(gate * 256 + hu) * 256 + k];
        Wsm2[k * 17 + row] = make_float2(wv, wv);
    }

    int lane = tid & 31, warp = tid >> 5;
    int nl = lane & 15;
    int bq = warp * 8 + (lane >> 4) * 4;      // local batch base (4 rows)
    int hu = j * 4 + (nl & 3);
    int n  = (nl >> 2) * 256 + hu;

    float gp[4];
    #pragma unroll
    for (int i2 = 0; i2 < 4; i2++)
        gp[i2] = g_gpre[(size_t)(t * 128 + bi * 64 + bq + i2) * 1024 + n];

    __syncthreads();

    ull acc0 = 0ull, acc1 = 0ull;
    #pragma unroll 8
    for (int k = 0; k < 256; k++) {
        int fs = ((k >> 2) & 7) << 2;
        ull w2 = *(const ull*)&Wsm2[k * 17 + nl];
        ulonglong2 hv = *(const ulonglong2*)&hsm[k * 64 + (bq ^ fs)];
        ffma2(acc0, w2, hv.x);
        ffma2(acc1, w2, hv.y);
    }
    float2 r0 = lo_hi(acc0), r1 = lo_hi(acc1);
    gsm[nl * 64 + bq + 0] = r0.x + gp[0];
    gsm[nl * 64 + bq + 1] = r0.y + gp[1];
    gsm[nl * 64 + bq + 2] = r1.x + gp[2];
    gsm[nl * 64 + bq + 3] = r1.y + gp[3];
    __syncthreads();

    // LSTM pointwise: 64 b x 4 hu = 256 elements -> 1 per thread
    int bl = tid & 63, hl = tid >> 6;
    float iv = gsm[(0 * 4 + hl) * 64 + bl];
    float fv = gsm[(1 * 4 + hl) * 64 + bl];
    float gv = gsm[(2 * 4 + hl) * 64 + bl];
    float ov = gsm[(3 * 4 + hl) * 64 + bl];
    int b   = bi * 64 + bl;
    int huo = j * 4 + hl;
    float c  = g_cstate[b * 256 + huo];
    float si = 1.f / (1.f + expf(-iv));
    float sf = 1.f / (1.f + expf(-fv));
    float so = 1.f / (1.f + expf(-ov));
    float c2 = sf * c + si * tanhf(gv);
    float h2 = so * tanhf(c2);
    g_cstate[b * 256 + huo] = c2;
    g_hbuf[par ^ 1][b * 256 + huo] = h2;
    g_Hs[(size_t)(b * 32 + t) * 256 + huo] = h2;
    if (hfinal) hfinal[b * 256 + huo] = h2;
}

// ---------------- launch ----------------
extern "C" void kernel_launch(void* const* d_in, const int* in_sizes, int n_in,
                              void* d_out, int out_size) {
    (void)in_sizes; (void)n_in; (void)out_size;
    const float* enc  = (const float*)d_in[0];
    const float* ench = (const float*)d_in[1];
    const float* encc = (const float*)d_in[2];
    const int*   tgt  = (const int*)  d_in[3];
    const float* emb  = (const float*)d_in[4];
    const float* Uat  = (const float*)d_in[6];
    const float* Vat  = (const float*)d_in[7];
    const float* Wih  = (const float*)d_in[8];
    const float* Whh  = (const float*)d_in[9];
    const float* bih  = (const float*)d_in[10];
    const float* bhh  = (const float*)d_in[11];
    const float* Wout = (const float*)d_in[12];
    const float* bout = (const float*)d_in[13];
    float* out      = (float*)d_out;
    float* out_h    = out + (size_t)128 * 32 * 16000;   // 65,536,000
    float* out_attn = out_h + 128 * 256;                // +32,768

    cudaFuncSetAttribute(k_step, cudaFuncAttributeMaxDynamicSharedMemorySize, STEP_SMEM_BYTES);

    k_init<<<128, 256>>>(ench, encc);
    k_prep<<<5, 256>>>(Vat, Uat, bih, bhh);
    k_embed<<<4096, 256>>>(tgt, emb);
    k_attn<<<128, 64>>>(enc, out_attn);
    k_ctx<<<128, 256>>>(enc);
    sgemm<0, 512, 512, 512, 1024><<<dim3(8, 32), 256>>>(Wih, nullptr, nullptr);
    for (int t = 0; t < 32; t++)
        k_step<<<128, 256, STEP_SMEM_BYTES>>>(Whh, t, t & 1, (t == 31) ? out_h : nullptr);
    sgemm<1, 256, 256, 256, 16000><<<dim3(125, 32), 256>>>(Wout, bout, out);
}

// round 8
// speedup vs baseline: 1.6296x; 1.6296x over previous
#include <cuda_runtime.h>
#include <cuda_bf16.h>
#include <cstdint>

typedef unsigned long long ull;

// Problem sizes: B=128, S=64, H=256, E=256, V=16000, T=32, START=1
// Output: decoder_outputs [128,32,16000] ++ h [1,128,256] ++ attentions [128,32,64]

// ---------------- device scratch (no mallocs allowed) ----------------
__device__ __align__(16) float g_u[256];            // u[h] = sum_g V[g]*U[g,h]
__device__ __align__(16) float g_bsum[1024];        // b_ih + b_hh
__device__ __align__(16) float g_w[128 * 64];       // attention weights (step-invariant)
__device__ __align__(16) float g_gpre[4096 * 1024]; // X @ W_ih.T + bsum
__device__ __align__(16) float g_hbuf[2][128 * 256];
__device__ __align__(16) float g_cstate[128 * 256];
__device__ __align__(16) __nv_bfloat16 g_Xhi[4096 * 512];   // split-bf16 [emb_relu | ctx]
__device__ __align__(16) __nv_bfloat16 g_Xlo[4096 * 512];
__device__ __align__(16) __nv_bfloat16 g_WihHi[1024 * 512]; // split-bf16 W_ih
__device__ __align__(16) __nv_bfloat16 g_WihLo[1024 * 512];
__device__ __align__(16) __nv_bfloat16 g_Hhi[4096 * 256];   // split-bf16 hidden states
__device__ __align__(16) __nv_bfloat16 g_Hlo[4096 * 256];
__device__ __align__(16) __nv_bfloat16 g_Whi[16000 * 256];  // split-bf16 W_out
__device__ __align__(16) __nv_bfloat16 g_Wlo[16000 * 256];

// ---------------- f32x2 helpers (PTX-only packed FMA, for LSTM step) ----------------
__device__ __forceinline__ void ffma2(ull &c, ull a, ull b) {
    asm("fma.rn.f32x2 %0, %1, %2, %0;" : "+l"(c) : "l"(a), "l"(b));
}
__device__ __forceinline__ float2 lo_hi(ull v) {
    float2 r; asm("mov.b64 {%0, %1}, %2;" : "=f"(r.x), "=f"(r.y) : "l"(v)); return r;
}

// ---------------- mma.sync helpers (family-level PTX; no tcgen05 on this target) ----
__device__ __forceinline__ uint32_t smem_u32(const void* p) {
    uint32_t a;
    asm("{ .reg .u64 t; cvta.to.shared.u64 t, %1; cvt.u32.u64 %0, t; }" : "=r"(a) : "l"(p));
    return a;
}
__device__ __forceinline__ void ldsm4(uint32_t* r, uint32_t addr) {
    asm volatile("ldmatrix.sync.aligned.m8n8.x4.shared.b16 {%0,%1,%2,%3}, [%4];"
        : "=r"(r[0]), "=r"(r[1]), "=r"(r[2]), "=r"(r[3]) : "r"(addr));
}
__device__ __forceinline__ void mma16816(float* c, const uint32_t* a, const uint32_t* b) {
    asm volatile("mma.sync.aligned.m16n8k16.row.col.f32.bf16.bf16.f32 "
        "{%0,%1,%2,%3}, {%4,%5,%6,%7}, {%8,%9}, {%0,%1,%2,%3};"
        : "+f"(c[0]), "+f"(c[1]), "+f"(c[2]), "+f"(c[3])
        : "r"(a[0]), "r"(a[1]), "r"(a[2]), "r"(a[3]), "r"(b[0]), "r"(b[1]));
}
#define SWZ(x) ((x) ^ (((x) >> 3) & 0x70))

// ---------------- init: copy initial h / c ----------------
__global__ void k_init(const float* __restrict__ eh, const float* __restrict__ ec) {
    int i = blockIdx.x * 256 + threadIdx.x;
    g_hbuf[0][i] = eh[i];
    g_cstate[i]  = ec[i];
}

// ---------------- prep: u = V @ U_attn ; bsum = b_ih + b_hh ----------------
__global__ void k_prep(const float* __restrict__ Vat, const float* __restrict__ Uat,
                       const float* __restrict__ bih, const float* __restrict__ bhh) {
    int tid = threadIdx.x;
    if (blockIdx.x == 0) {
        float a = 0.f;
        for (int g = 0; g < 256; g++) a += Vat[g] * Uat[g * 256 + tid];
        g_u[tid] = a;
    } else {
        int nn = (blockIdx.x - 1) * 256 + tid;
        g_bsum[nn] = bih[nn] + bhh[nn];
    }
}

// ---------------- split conversions ----------------
__global__ void k_cvtW(const float* __restrict__ Wout) {
    int i = blockIdx.x * 256 + threadIdx.x;       // grid 16000
    float w = Wout[i];
    __nv_bfloat16 hi = __float2bfloat16(w);
    g_Whi[i] = hi;
    g_Wlo[i] = __float2bfloat16(w - __bfloat162float(hi));
}
__global__ void k_cvtWih(const float* __restrict__ Wih) {
    int i = blockIdx.x * 256 + threadIdx.x;       // grid 2048
    float w = Wih[i];
    __nv_bfloat16 hi = __float2bfloat16(w);
    g_WihHi[i] = hi;
    g_WihLo[i] = __float2bfloat16(w - __bfloat162float(hi));
}

// ---------------- embedding gather + relu -> split X[:, 0:256] ----------------
__global__ void k_embed(const int* __restrict__ tgt, const float* __restrict__ emb) {
    int r = blockIdx.x;           // t*128 + b, grid 4096
    int t = r >> 7, b = r & 127;
    int tok = (t == 0) ? 1 : tgt[b * 32 + (t - 1)];
    float v = fmaxf(emb[(size_t)tok * 256 + threadIdx.x], 0.f);
    __nv_bfloat16 hi = __float2bfloat16(v);
    size_t idx = (size_t)r * 512 + threadIdx.x;
    g_Xhi[idx] = hi;
    g_Xlo[idx] = __float2bfloat16(v - __bfloat162float(hi));
}

// ---------------- attention scores + softmax (step-invariant) ----------------
__global__ void k_attn(const float* __restrict__ enc, float* __restrict__ out_attn) {
    __shared__ float usm[256];
    __shared__ float sc[64];
    int b = blockIdx.x, s = threadIdx.x;    // 128 blocks x 64 threads
    for (int i = s; i < 256; i += 64) usm[i] = g_u[i];
    __syncthreads();
    const float4* row = (const float4*)(enc + ((size_t)b * 64 + s) * 256);
    float acc = 0.f;
    #pragma unroll 8
    for (int k = 0; k < 64; k++) {
        float4 e = row[k];
        acc += e.x * usm[k*4] + e.y * usm[k*4+1] + e.z * usm[k*4+2] + e.w * usm[k*4+3];
    }
    sc[s] = acc; __syncthreads();
    float m = sc[0];
    for (int i = 1; i < 64; i++) m = fmaxf(m, sc[i]);
    float e = expf(acc - m);
    __syncthreads();
    sc[s] = e; __syncthreads();
    float sum = 0.f;
    for (int i = 0; i < 64; i++) sum += sc[i];
    float w = e / sum;
    g_w[b * 64 + s] = w;
    #pragma unroll
    for (int t = 0; t < 32; t++) out_attn[(size_t)b * 2048 + t * 64 + s] = w;
}

// ---------------- context = w @ enc ; broadcast -> split X[:, 256:512] ----------------
__global__ void k_ctx(const float* __restrict__ enc) {
    __shared__ float wsh[64];
    int b = blockIdx.x, h = threadIdx.x;    // 128 blocks x 256 threads
    if (h < 64) wsh[h] = g_w[b * 64 + h];
    __syncthreads();
    float acc = 0.f;
    #pragma unroll 8
    for (int s = 0; s < 64; s++) acc += wsh[s] * enc[((size_t)b * 64 + s) * 256 + h];
    __nv_bfloat16 hi = __float2bfloat16(acc);
    __nv_bfloat16 lo = __float2bfloat16(acc - __bfloat162float(hi));
    #pragma unroll
    for (int t = 0; t < 32; t++) {
        size_t idx = (size_t)(t * 128 + b) * 512 + 256 + h;
        g_Xhi[idx] = hi;
        g_Xlo[idx] = lo;
    }
}

// ---------------- split-bf16 HMMA GEMM: C = Ahi*Bhi^T + Ahi*Blo^T + Alo*Bhi^T + bias ---
// Block 128x128 C-tile, 8 warps (2 row x 4 col), warp tile 64x32.
// K chunked by 64 into 64KB SW128 smem (tiles: Ahi@0 Alo@16K Bhi@32K Blo@48K).
// MODE 0: A=g_X (K=512), B=g_Wih, bias=g_bsum, C=g_gpre (ld 1024)
// MODE 1: A=g_H (K=256), B=g_Wout, bias=arg,   C=arg    (ld 16000)
__device__ __forceinline__ void load_tile64(char* dst, const __nv_bfloat16* src,
                                            int ldk, int tid) {
    #pragma unroll
    for (int i = 0; i < 4; i++) {
        int u = i * 256 + tid;       // 0..1023 16B-units; 8 per 128B row
        int r = u >> 3, kb = (u & 7) * 16;
        uint4 v = *(const uint4*)((const char*)src + (size_t)r * (ldk * 2) + kb);
        *(uint4*)(dst + SWZ(r * 128 + kb)) = v;
    }
}

template<int MODE>
__global__ __launch_bounds__(256, 2) void gemm_mma(const float* __restrict__ bias_ext,
                                                   float* __restrict__ Cext) {
    constexpr int KK  = (MODE == 0) ? 512 : 256;
    constexpr int LDC = (MODE == 0) ? 1024 : 16000;
    const __nv_bfloat16* Ahi = (MODE == 0) ? g_Xhi   : g_Hhi;
    const __nv_bfloat16* Alo = (MODE == 0) ? g_Xlo   : g_Hlo;
    const __nv_bfloat16* Bhi = (MODE == 0) ? g_WihHi : g_Whi;
    const __nv_bfloat16* Blo = (MODE == 0) ? g_WihLo : g_Wlo;
    const float* bias = (MODE == 0) ? g_bsum : bias_ext;
    float*       C    = (MODE == 0) ? g_gpre : Cext;

    extern __shared__ char ts[];
    uint32_t sb = smem_u32(ts);
    int tid = threadIdx.x, lane = tid & 31, wid = tid >> 5;
    int m0 = blockIdx.y * 128, n0 = blockIdx.x * 128;
    int wm = (wid & 1) * 64, wn = (wid >> 1) * 32;

    // Precomputed swizzled ldmatrix offsets; per-kstep update is ^ (ks<<5)
    // (kx bits 5-6 are zero in the pre-swizzle column byte, and the swizzle
    //  source bits 7-9 are row bits unaffected by kx -> SWZ(x+kx) = SWZ(x)^kx).
    uint32_t aswz[4], bswz[2];
    {
        int al = lane & 15, ah = (lane >> 4) << 4;
        #pragma unroll
        for (int fr = 0; fr < 4; fr++)
            aswz[fr] = SWZ((uint32_t)((wm + fr * 16 + al) * 128 + ah));
        int nl = (lane & 7) + ((lane >> 4) & 1) * 8;
        int kh = ((lane >> 3) & 1) << 4;
        #pragma unroll
        for (int fb = 0; fb < 2; fb++)
            bswz[fb] = SWZ((uint32_t)((wn + fb * 16 + nl) * 128 + kh));
    }

    float acc[4][4][4];
    #pragma unroll
    for (int i = 0; i < 4; i++)
        #pragma unroll
        for (int j = 0; j < 4; j++)
            #pragma unroll
            for (int q = 0; q < 4; q++) acc[i][j][q] = 0.f;

    const __nv_bfloat16* Ah = Ahi + (size_t)m0 * KK;
    const __nv_bfloat16* Al = Alo + (size_t)m0 * KK;
    const __nv_bfloat16* Bh = Bhi + (size_t)n0 * KK;
    const __nv_bfloat16* Bl = Blo + (size_t)n0 * KK;

    #pragma unroll 1
    for (int c = 0; c < KK / 64; c++) {
        __syncthreads();                       // prior chunk's ldmatrix done
        load_tile64(ts +     0, Ah + c * 64, KK, tid);
        load_tile64(ts + 16384, Al + c * 64, KK, tid);
        load_tile64(ts + 32768, Bh + c * 64, KK, tid);
        load_tile64(ts + 49152, Bl + c * 64, KK, tid);
        __syncthreads();
        #pragma unroll
        for (int ks = 0; ks < 4; ks++) {
            uint32_t kx = (uint32_t)(ks << 5);
            uint32_t bh[8], bl[8];
            ldsm4(bh + 0, sb + 32768 + (bswz[0] ^ kx));
            ldsm4(bh + 4, sb + 32768 + (bswz[1] ^ kx));
            ldsm4(bl + 0, sb + 49152 + (bswz[0] ^ kx));
            ldsm4(bl + 4, sb + 49152 + (bswz[1] ^ kx));
            #pragma unroll
            for (int fr = 0; fr < 4; fr++) {
                uint32_t a[4], a2[4];
                ldsm4(a, sb + (aswz[fr] ^ kx));                 // A_hi
                #pragma unroll
                for (int fc = 0; fc < 4; fc++) mma16816(acc[fr][fc], a, bh + fc * 2);
                #pragma unroll
                for (int fc = 0; fc < 4; fc++) mma16816(acc[fr][fc], a, bl + fc * 2);
                ldsm4(a2, sb + 16384 + (aswz[fr] ^ kx));        // A_lo
                #pragma unroll
                for (int fc = 0; fc < 4; fc++) mma16816(acc[fr][fc], a2, bh + fc * 2);
            }
        }
    }

    // epilogue: c0,c1 -> (row, col..col+1); c2,c3 -> (row+8, ...)
    int r0 = m0 + wm + (lane >> 2);
    int cb = n0 + wn + (lane & 3) * 2;
    #pragma unroll
    for (int fr = 0; fr < 4; fr++) {
        #pragma unroll
        for (int fc = 0; fc < 4; fc++) {
            int row = r0 + fr * 16;
            int col = cb + fc * 8;
            float2 b2 = *(const float2*)&bias[col];
            float2 o0 = make_float2(acc[fr][fc][0] + b2.x, acc[fr][fc][1] + b2.y);
            float2 o1 = make_float2(acc[fr][fc][2] + b2.x, acc[fr][fc][3] + b2.y);
            *(float2*)&C[(size_t)row * LDC + col]       = o0;
            *(float2*)&C[(size_t)(row + 8) * LDC + col] = o1;
        }
    }
}

// ---------------- recurrent step: gates = gpre + h@W_hh^T ; LSTM pointwise ----------------
#define STEP_SMEM_FLOATS (256*64 + 256*17*2 + 16*64)
#define STEP_SMEM_BYTES  (STEP_SMEM_FLOATS * 4)

__global__ __launch_bounds__(256) void k_step(const float* __restrict__ Whh, int t, int par,
                                              float* __restrict__ hfinal) {
    extern __shared__ __align__(16) float sm[];
    float*  hsm  = sm;                              // [k 256][b 64], XOR-swizzled
    float2* Wsm2 = (float2*)(sm + 256 * 64);        // [k 256][row 16] dup pairs, stride 17
    float*  gsm  = sm + 256 * 64 + 256 * 17 * 2;    // [16][64]

    int tid = threadIdx.x;
    int j  = blockIdx.x & 63;
    int bi = blockIdx.x >> 6;

    const float* hprev = g_hbuf[par] + bi * 64 * 256;

    #pragma unroll
    for (int i = 0; i < 16; i++) {
        int idx = tid + i * 256;
        int bl = idx >> 6;
        int kq = (idx & 63) << 2;
        float4 v = *(const float4*)&hprev[bl * 256 + kq];
        float vv[4] = {v.x, v.y, v.z, v.w};
        #pragma unroll
        for (int d = 0; d < 4; d++) {
            int k = kq + d;
            int fs = ((k >> 2) & 7) << 2;
            hsm[k * 64 + (bl ^ fs)] = vv[d];
        }
    }
    #pragma unroll
    for (int i = 0; i < 16; i++) {
        int idx = tid + i * 256;
        int row = idx >> 8;
        int k   = idx & 255;
        int hu   = j * 4 + (row & 3);
        int gate = row >> 2;
        float wv = Whh[(gate * 256 + hu) * 256 + k];
        Wsm2[k * 17 + row] = make_float2(wv, wv);
    }

    int lane = tid & 31, warp = tid >> 5;
    int nl = lane & 15;
    int bq = warp * 8 + (lane >> 4) * 4;
    int hu = j * 4 + (nl & 3);
    int n  = (nl >> 2) * 256 + hu;

    float gp[4];
    #pragma unroll
    for (int i2 = 0; i2 < 4; i2++)
        gp[i2] = g_gpre[(size_t)(t * 128 + bi * 64 + bq + i2) * 1024 + n];

    __syncthreads();

    ull acc0 = 0ull, acc1 = 0ull;
    #pragma unroll 8
    for (int k = 0; k < 256; k++) {
        int fs = ((k >> 2) & 7) << 2;
        ull w2 = *(const ull*)&Wsm2[k * 17 + nl];
        ulonglong2 hv = *(const ulonglong2*)&hsm[k * 64 + (bq ^ fs)];
        ffma2(acc0, w2, hv.x);
        ffma2(acc1, w2, hv.y);
    }
    float2 r0 = lo_hi(acc0), r1 = lo_hi(acc1);
    gsm[nl * 64 + bq + 0] = r0.x + gp[0];
    gsm[nl * 64 + bq + 1] = r0.y + gp[1];
    gsm[nl * 64 + bq + 2] = r1.x + gp[2];
    gsm[nl * 64 + bq + 3] = r1.y + gp[3];
    __syncthreads();

    int bl = tid & 63, hl = tid >> 6;
    float iv = gsm[(0 * 4 + hl) * 64 + bl];
    float fv = gsm[(1 * 4 + hl) * 64 + bl];
    float gv = gsm[(2 * 4 + hl) * 64 + bl];
    float ov = gsm[(3 * 4 + hl) * 64 + bl];
    int b   = bi * 64 + bl;
    int huo = j * 4 + hl;
    float c  = g_cstate[b * 256 + huo];
    float si = 1.f / (1.f + expf(-iv));
    float sf = 1.f / (1.f + expf(-fv));
    float so = 1.f / (1.f + expf(-ov));
    float c2 = sf * c + si * tanhf(gv);
    float h2 = so * tanhf(c2);
    g_cstate[b * 256 + huo] = c2;
    g_hbuf[par ^ 1][b * 256 + huo] = h2;
    __nv_bfloat16 hhi = __float2bfloat16(h2);
    size_t hidx = (size_t)(b * 32 + t) * 256 + huo;
    g_Hhi[hidx] = hhi;
    g_Hlo[hidx] = __float2bfloat16(h2 - __bfloat162float(hhi));
    if (hfinal) hfinal[b * 256 + huo] = h2;
}

// ---------------- launch ----------------
#define GEMM_SMEM 65536

extern "C" void kernel_launch(void* const* d_in, const int* in_sizes, int n_in,
                              void* d_out, int out_size) {
    (void)in_sizes; (void)n_in; (void)out_size;
    const float* enc  = (const float*)d_in[0];
    const float* ench = (const float*)d_in[1];
    const float* encc = (const float*)d_in[2];
    const int*   tgt  = (const int*)  d_in[3];
    const float* emb  = (const float*)d_in[4];
    const float* Uat  = (const float*)d_in[6];
    const float* Vat  = (const float*)d_in[7];
    const float* Wih  = (const float*)d_in[8];
    const float* Whh  = (const float*)d_in[9];
    const float* bih  = (const float*)d_in[10];
    const float* bhh  = (const float*)d_in[11];
    const float* Wout = (const float*)d_in[12];
    const float* bout = (const float*)d_in[13];
    float* out      = (float*)d_out;
    float* out_h    = out + (size_t)128 * 32 * 16000;   // 65,536,000
    float* out_attn = out_h + 128 * 256;                // +32,768

    cudaFuncSetAttribute(k_step, cudaFuncAttributeMaxDynamicSharedMemorySize, STEP_SMEM_BYTES);
    cudaFuncSetAttribute(gemm_mma<0>, cudaFuncAttributeMaxDynamicSharedMemorySize, GEMM_SMEM);
    cudaFuncSetAttribute(gemm_mma<1>, cudaFuncAttributeMaxDynamicSharedMemorySize, GEMM_SMEM);

    k_init<<<128, 256>>>(ench, encc);
    k_prep<<<5, 256>>>(Vat, Uat, bih, bhh);
    k_cvtW<<<16000, 256>>>(Wout);
    k_cvtWih<<<2048, 256>>>(Wih);
    k_embed<<<4096, 256>>>(tgt, emb);
    k_attn<<<128, 64>>>(enc, out_attn);
    k_ctx<<<128, 256>>>(enc);
    gemm_mma<0><<<dim3(8, 32), 256, GEMM_SMEM>>>(nullptr, nullptr);
    for (int t = 0; t < 32; t++)
        k_step<<<128, 256, STEP_SMEM_BYTES>>>(Whh, t, t & 1, (t == 31) ? out_h : nullptr);
    gemm_mma<1><<<dim3(125, 32), 256, GEMM_SMEM>>>(bout, out);
}

// round 16
// speedup vs baseline: 1.6756x; 1.0282x over previous
#include <cuda_runtime.h>
#include <cuda_bf16.h>
#include <cstdint>

typedef unsigned long long ull;

// Problem sizes: B=128, S=64, H=256, E=256, V=16000, T=32, START=1
// Output: decoder_outputs [128,32,16000] ++ h [1,128,256] ++ attentions [128,32,64]

// ---------------- device scratch (no mallocs allowed) ----------------
__device__ __align__(16) float g_u[256];            // u[h] = sum_g V[g]*U[g,h]
__device__ __align__(16) float g_bsum[1024];        // b_ih + b_hh
__device__ __align__(16) float g_w[128 * 64];       // attention weights (step-invariant)
__device__ __align__(16) float g_gpre[4096 * 1024]; // X @ W_ih.T + bsum
__device__ __align__(16) float g_hbuf[2][128 * 256];
__device__ __align__(16) float g_cstate[128 * 256];
__device__ __align__(16) __nv_bfloat16 g_Xhi[4096 * 512];   // split-bf16 [emb_relu | ctx]
__device__ __align__(16) __nv_bfloat16 g_Xlo[4096 * 512];
__device__ __align__(16) __nv_bfloat16 g_WihHi[1024 * 512]; // split-bf16 W_ih
__device__ __align__(16) __nv_bfloat16 g_WihLo[1024 * 512];
__device__ __align__(16) __nv_bfloat16 g_Hhi[4096 * 256];   // split-bf16 hidden states
__device__ __align__(16) __nv_bfloat16 g_Hlo[4096 * 256];
__device__ __align__(16) __nv_bfloat16 g_Whi[16000 * 256];  // split-bf16 W_out
__device__ __align__(16) __nv_bfloat16 g_Wlo[16000 * 256];

// ---------------- f32x2 helpers (PTX-only packed FMA, for LSTM step) ----------------
__device__ __forceinline__ void ffma2(ull &c, ull a, ull b) {
    asm("fma.rn.f32x2 %0, %1, %2, %0;" : "+l"(c) : "l"(a), "l"(b));
}
__device__ __forceinline__ float2 lo_hi(ull v) {
    float2 r; asm("mov.b64 {%0, %1}, %2;" : "=f"(r.x), "=f"(r.y) : "l"(v)); return r;
}

// ---------------- mma.sync / cp.async helpers (family-level PTX) ----------------
__device__ __forceinline__ uint32_t smem_u32(const void* p) {
    uint32_t a;
    asm("{ .reg .u64 t; cvta.to.shared.u64 t, %1; cvt.u32.u64 %0, t; }" : "=r"(a) : "l"(p));
    return a;
}
__device__ __forceinline__ void ldsm4(uint32_t* r, uint32_t addr) {
    asm volatile("ldmatrix.sync.aligned.m8n8.x4.shared.b16 {%0,%1,%2,%3}, [%4];"
        : "=r"(r[0]), "=r"(r[1]), "=r"(r[2]), "=r"(r[3]) : "r"(addr));
}
__device__ __forceinline__ void mma16816(float* c, const uint32_t* a, const uint32_t* b) {
    asm volatile("mma.sync.aligned.m16n8k16.row.col.f32.bf16.bf16.f32 "
        "{%0,%1,%2,%3}, {%4,%5,%6,%7}, {%8,%9}, {%0,%1,%2,%3};"
        : "+f"(c[0]), "+f"(c[1]), "+f"(c[2]), "+f"(c[3])
        : "r"(a[0]), "r"(a[1]), "r"(a[2]), "r"(a[3]), "r"(b[0]), "r"(b[1]));
}
__device__ __forceinline__ void cp16(uint32_t dst, const void* src) {
    asm volatile("cp.async.ca.shared.global [%0], [%1], 16;" :: "r"(dst), "l"(src));
}
#define CP_COMMIT() asm volatile("cp.async.commit_group;" ::: "memory")
#define SWZ(x) ((x) ^ (((x) >> 3) & 0x70))

__device__ __forceinline__ uint32_t pack2bf(float a, float b) {
    __nv_bfloat16 ha = __float2bfloat16(a), hb = __float2bfloat16(b);
    return ((uint32_t)__bfloat16_as_ushort(hb) << 16) | __bfloat16_as_ushort(ha);
}

// ---------------- init: copy initial h / c ----------------
__global__ void k_init(const float* __restrict__ eh, const float* __restrict__ ec) {
    int i = blockIdx.x * 256 + threadIdx.x;
    g_hbuf[0][i] = eh[i];
    g_cstate[i]  = ec[i];
}

// ---------------- prep: u = V @ U_attn ; bsum = b_ih + b_hh ----------------
__global__ void k_prep(const float* __restrict__ Vat, const float* __restrict__ Uat,
                       const float* __restrict__ bih, const float* __restrict__ bhh) {
    int tid = threadIdx.x;
    if (blockIdx.x == 0) {
        float a = 0.f;
        for (int g = 0; g < 256; g++) a += Vat[g] * Uat[g * 256 + tid];
        g_u[tid] = a;
    } else {
        int nn = (blockIdx.x - 1) * 256 + tid;
        g_bsum[nn] = bih[nn] + bhh[nn];
    }
}

// ---------------- split conversion (vectorized float4): mode 0 = W_ih, 1 = W_out ----
__global__ void k_cvt(const float* __restrict__ W, int mode) {
    size_t i = ((size_t)blockIdx.x * 256 + threadIdx.x) * 4;
    float4 w = *(const float4*)(W + i);
    __nv_bfloat16 h0 = __float2bfloat16(w.x), h1 = __float2bfloat16(w.y);
    __nv_bfloat16 h2 = __float2bfloat16(w.z), h3 = __float2bfloat16(w.w);
    uint2 hp;
    hp.x = ((uint32_t)__bfloat16_as_ushort(h1) << 16) | __bfloat16_as_ushort(h0);
    hp.y = ((uint32_t)__bfloat16_as_ushort(h3) << 16) | __bfloat16_as_ushort(h2);
    uint2 lp;
    lp.x = pack2bf(w.x - __bfloat162float(h0), w.y - __bfloat162float(h1));
    lp.y = pack2bf(w.z - __bfloat162float(h2), w.w - __bfloat162float(h3));
    __nv_bfloat16* hi = mode ? g_Whi : g_WihHi;
    __nv_bfloat16* lo = mode ? g_Wlo : g_WihLo;
    *(uint2*)(hi + i) = hp;
    *(uint2*)(lo + i) = lp;
}

// ---------------- embedding gather + relu -> split X[:, 0:256] (float4) ----------------
__global__ void k_embed(const int* __restrict__ tgt, const float* __restrict__ emb) {
    int r = blockIdx.x;           // t*128 + b, grid 4096, 64 threads
    int t = r >> 7, b = r & 127;
    int tok = (t == 0) ? 1 : tgt[b * 32 + (t - 1)];
    float4 v = ((const float4*)(emb + (size_t)tok * 256))[threadIdx.x];
    v.x = fmaxf(v.x, 0.f); v.y = fmaxf(v.y, 0.f);
    v.z = fmaxf(v.z, 0.f); v.w = fmaxf(v.w, 0.f);
    __nv_bfloat16 h0 = __float2bfloat16(v.x), h1 = __float2bfloat16(v.y);
    __nv_bfloat16 h2 = __float2bfloat16(v.z), h3 = __float2bfloat16(v.w);
    uint2 hp;
    hp.x = ((uint32_t)__bfloat16_as_ushort(h1) << 16) | __bfloat16_as_ushort(h0);
    hp.y = ((uint32_t)__bfloat16_as_ushort(h3) << 16) | __bfloat16_as_ushort(h2);
    uint2 lp;
    lp.x = pack2bf(v.x - __bfloat162float(h0), v.y - __bfloat162float(h1));
    lp.y = pack2bf(v.z - __bfloat162float(h2), v.w - __bfloat162float(h3));
    size_t base = (size_t)r * 512 + threadIdx.x * 4;
    *(uint2*)(g_Xhi + base) = hp;
    *(uint2*)(g_Xlo + base) = lp;
}

// ---------------- attention scores + softmax (step-invariant), 256 threads ----------
__global__ void k_attn(const float* __restrict__ enc, float* __restrict__ out_attn) {
    __shared__ float usm[256];
    __shared__ float part[256];
    __shared__ float sc[64];
    int b = blockIdx.x, tid = threadIdx.x;
    int s = tid & 63, q = tid >> 6;
    usm[tid] = g_u[tid];
    __syncthreads();
    const float4* row = (const float4*)(enc + ((size_t)b * 64 + s) * 256 + q * 64);
    float acc = 0.f;
    #pragma unroll
    for (int k = 0; k < 16; k++) {
        float4 e = row[k];
        int u = q * 64 + k * 4;
        acc += e.x * usm[u] + e.y * usm[u+1] + e.z * usm[u+2] + e.w * usm[u+3];
    }
    part[q * 64 + s] = acc;
    __syncthreads();
    if (tid < 64) sc[s] = part[s] + part[64 + s] + part[128 + s] + part[192 + s];
    __syncthreads();
    if (tid < 64) {
        float m = sc[0];
        #pragma unroll 8
        for (int i = 1; i < 64; i++) m = fmaxf(m, sc[i]);
        part[s] = expf(sc[s] - m);
    }
    __syncthreads();
    if (tid < 64) {
        float sum = 0.f;
        #pragma unroll 8
        for (int i = 0; i < 64; i++) sum += part[i];
        float w = part[s] / sum;
        sc[s] = w;
        g_w[b * 64 + s] = w;
    }
    __syncthreads();
    float w = sc[s];
    #pragma unroll
    for (int t0 = 0; t0 < 8; t0++)
        out_attn[(size_t)b * 2048 + (q * 8 + t0) * 64 + s] = w;
}

// ---------------- context = w @ enc ; broadcast -> split X[:, 256:512] ----------------
__global__ void k_ctx(const float* __restrict__ enc) {
    __shared__ float wsh[64];
    int b = blockIdx.x, h = threadIdx.x;    // 128 blocks x 256 threads
    if (h < 64) wsh[h] = g_w[b * 64 + h];
    __syncthreads();
    float acc = 0.f;
    #pragma unroll 8
    for (int s = 0; s < 64; s++) acc += wsh[s] * enc[((size_t)b * 64 + s) * 256 + h];
    __nv_bfloat16 hi = __float2bfloat16(acc);
    __nv_bfloat16 lo = __float2bfloat16(acc - __bfloat162float(hi));
    #pragma unroll
    for (int t = 0; t < 32; t++) {
        size_t idx = (size_t)(t * 128 + b) * 512 + 256 + h;
        g_Xhi[idx] = hi;
        g_Xlo[idx] = lo;
    }
}

// ---------------- split-bf16 HMMA GEMM, cp.async 2-stage pipeline ----------------
// Block 128x128 C-tile, 8 warps (2 row x 4 col), warp tile 64x32.
// K chunked by 32. Stage = 4 tiles x 8KB = 32KB; 2 stages = 64KB -> 2 CTAs/SM.
// Tile layout: logical [128 rows][64B]; physical packs 2 rows per 128B smem row:
//   pbyte(r, cb) = (r>>1)*128 + (r&1)*64 + cb, then SW128 swizzle.
// k-step XOR trick: kx = ks*32 (bit 5) is 0 in all precomputed pre-swizzle bytes and
// disjoint from swizzle source bits 7-9  ->  SWZ(x + kx) = SWZ(x) ^ kx.
// MODE 0: A=g_X (K=512), B=g_Wih, bias=g_bsum, C=g_gpre (ld 1024)
// MODE 1: A=g_H (K=256), B=g_Wout, bias=arg,   C=arg    (ld 16000)
__device__ __forceinline__ void pj_issue(uint32_t sbase,
    const char* Ah, const char* Al, const char* Bh, const char* Bl,
    int ldb, int tid)
{
    const char* s4[4] = {Ah, Al, Bh, Bl};
    #pragma unroll
    for (int tgt = 0; tgt < 4; tgt++) {
        #pragma unroll
        for (int i = 0; i < 2; i++) {
            int u = tid + i * 256;          // 0..511 16B-units
            int r = u >> 2, c16 = u & 3;
            uint32_t pb = (uint32_t)((r >> 1) * 128 + (r & 1) * 64 + c16 * 16);
            cp16(sbase + tgt * 8192 + SWZ(pb), s4[tgt] + (size_t)r * ldb + c16 * 16);
        }
    }
}

template<int MODE>
__global__ __launch_bounds__(256, 2) void gemm_mma(const float* __restrict__ bias_ext,
                                                   float* __restrict__ Cext) {
    constexpr int KK  = (MODE == 0) ? 512 : 256;
    constexpr int LDC = (MODE == 0) ? 1024 : 16000;
    constexpr int NCH = KK / 32;
    const __nv_bfloat16* Ahi = (MODE == 0) ? g_Xhi   : g_Hhi;
    const __nv_bfloat16* Alo = (MODE == 0) ? g_Xlo   : g_Hlo;
    const __nv_bfloat16* Bhi = (MODE == 0) ? g_WihHi : g_Whi;
    const __nv_bfloat16* Blo = (MODE == 0) ? g_WihLo : g_Wlo;
    const float* bias = (MODE == 0) ? g_bsum : bias_ext;
    float*       C    = (MODE == 0) ? g_gpre : Cext;

    extern __shared__ char ts[];
    uint32_t sb = smem_u32(ts);
    int tid = threadIdx.x, lane = tid & 31, wid = tid >> 5;
    int m0 = blockIdx.y * 128, n0 = blockIdx.x * 128;
    int wm = (wid & 1) * 64, wn = (wid >> 1) * 32;

    const char* Ah = (const char*)(Ahi + (size_t)m0 * KK);
    const char* Al = (const char*)(Alo + (size_t)m0 * KK);
    const char* Bh = (const char*)(Bhi + (size_t)n0 * KK);
    const char* Bl = (const char*)(Blo + (size_t)n0 * KK);

    // precomputed swizzled ldmatrix offsets (packed 2-rows-per-128B layout)
    uint32_t aswz[4], bswz[2];
    {
        int al = lane & 15, ah = ((lane >> 4) & 1) * 16;
        #pragma unroll
        for (int fr = 0; fr < 4; fr++) {
            int r = wm + fr * 16 + al;
            aswz[fr] = SWZ((uint32_t)((r >> 1) * 128 + (r & 1) * 64 + ah));
        }
        int nl = (lane & 7) + ((lane >> 4) & 1) * 8;
        int kh = ((lane >> 3) & 1) * 16;
        #pragma unroll
        for (int fb = 0; fb < 2; fb++) {
            int r = wn + fb * 16 + nl;
            bswz[fb] = SWZ((uint32_t)((r >> 1) * 128 + (r & 1) * 64 + kh));
        }
    }

    float acc[4][4][4];
    #pragma unroll
    for (int i = 0; i < 4; i++)
        #pragma unroll
        for (int j = 0; j < 4; j++)
            #pragma unroll
            for (int q = 0; q < 4; q++) acc[i][j][q] = 0.f;

    // prologue: stage 0
    pj_issue(sb, Ah, Al, Bh, Bl, KK * 2, tid);
    CP_COMMIT();

    #pragma unroll 1
    for (int c = 0; c < NCH; c++) {
        if (c + 1 < NCH) {
            int coff = (c + 1) * 64;             // byte offset along K
            pj_issue(sb + ((c + 1) & 1) * 32768,
                     Ah + coff, Al + coff, Bh + coff, Bl + coff, KK * 2, tid);
            CP_COMMIT();
            asm volatile("cp.async.wait_group 1;" ::: "memory");
        } else {
            asm volatile("cp.async.wait_group 0;" ::: "memory");
        }
        __syncthreads();
        uint32_t bb = sb + (c & 1) * 32768;
        #pragma unroll
        for (int ks = 0; ks < 2; ks++) {
            uint32_t kx = (uint32_t)(ks << 5);
            uint32_t bh[8], bl[8];
            ldsm4(bh + 0, bb + 16384 + (bswz[0] ^ kx));
            ldsm4(bh + 4, bb + 16384 + (bswz[1] ^ kx));
            ldsm4(bl + 0, bb + 24576 + (bswz[0] ^ kx));
            ldsm4(bl + 4, bb + 24576 + (bswz[1] ^ kx));
            #pragma unroll
            for (int fr = 0; fr < 4; fr++) {
                uint32_t a[4], a2[4];
                ldsm4(a, bb + (aswz[fr] ^ kx));                 // A_hi
                #pragma unroll
                for (int fc = 0; fc < 4; fc++) mma16816(acc[fr][fc], a, bh + fc * 2);
                #pragma unroll
                for (int fc = 0; fc < 4; fc++) mma16816(acc[fr][fc], a, bl + fc * 2);
                ldsm4(a2, bb + 8192 + (aswz[fr] ^ kx));         // A_lo
                #pragma unroll
                for (int fc = 0; fc < 4; fc++) mma16816(acc[fr][fc], a2, bh + fc * 2);
            }
        }
        __syncthreads();   // all warps done with buffer (c&1) before it is refilled
    }

    // epilogue: c0,c1 -> (row, col..col+1); c2,c3 -> (row+8, ...)
    int r0 = m0 + wm + (lane >> 2);
    int cb = n0 + wn + (lane & 3) * 2;
    #pragma unroll
    for (int fr = 0; fr < 4; fr++) {
        #pragma unroll
        for (int fc = 0; fc < 4; fc++) {
            int row = r0 + fr * 16;
            int col = cb + fc * 8;
            float2 b2 = *(const float2*)&bias[col];
            float2 o0 = make_float2(acc[fr][fc][0] + b2.x, acc[fr][fc][1] + b2.y);
            float2 o1 = make_float2(acc[fr][fc][2] + b2.x, acc[fr][fc][3] + b2.y);
            *(float2*)&C[(size_t)row * LDC + col]       = o0;
            *(float2*)&C[(size_t)(row + 8) * LDC + col] = o1;
        }
    }
}

// ---------------- recurrent step: gates = gpre + h@W_hh^T ; LSTM pointwise ----------------
#define STEP_SMEM_FLOATS (256*64 + 256*17*2 + 16*64)
#define STEP_SMEM_BYTES  (STEP_SMEM_FLOATS * 4)

__global__ __launch_bounds__(256) void k_step(const float* __restrict__ Whh, int t, int par,
                                              float* __restrict__ hfinal) {
    extern __shared__ __align__(16) float sm[];
    float*  hsm  = sm;                              // [k 256][b 64], XOR-swizzled
    float2* Wsm2 = (float2*)(sm + 256 * 64);        // [k 256][row 16] dup pairs, stride 17
    float*  gsm  = sm + 256 * 64 + 256 * 17 * 2;    // [16][64]

    int tid = threadIdx.x;
    int j  = blockIdx.x & 63;
    int bi = blockIdx.x >> 6;

    const float* hprev = g_hbuf[par] + bi * 64 * 256;

    #pragma unroll
    for (int i = 0; i < 16; i++) {
        int idx = tid + i * 256;
        int bl = idx >> 6;
        int kq = (idx & 63) << 2;
        float4 v = *(const float4*)&hprev[bl * 256 + kq];
        float vv[4] = {v.x, v.y, v.z, v.w};
        #pragma unroll
        for (int d = 0; d < 4; d++) {
            int k = kq + d;
            int fs = ((k >> 2) & 7) << 2;
            hsm[k * 64 + (bl ^ fs)] = vv[d];
        }
    }
    #pragma unroll
    for (int i = 0; i < 16; i++) {
        int idx = tid + i * 256;
        int row = idx >> 8;
        int k   = idx & 255;
        int hu   = j * 4 + (row & 3);
        int gate = row >> 2;
        float wv = Whh[(gate * 256 + hu) * 256 + k];
        Wsm2[k * 17 + row] = make_float2(wv, wv);
    }

    int lane = tid & 31, warp = tid >> 5;
    int nl = lane & 15;
    int bq = warp * 8 + (lane >> 4) * 4;
    int hu = j * 4 + (nl & 3);
    int n  = (nl >> 2) * 256 + hu;

    float gp[4];
    #pragma unroll
    for (int i2 = 0; i2 < 4; i2++)
        gp[i2] = g_gpre[(size_t)(t * 128 + bi * 64 + bq + i2) * 1024 + n];

    __syncthreads();

    ull acc0 = 0ull, acc1 = 0ull;
    #pragma unroll 8
    for (int k = 0; k < 256; k++) {
        int fs = ((k >> 2) & 7) << 2;
        ull w2 = *(const ull*)&Wsm2[k * 17 + nl];
        ulonglong2 hv = *(const ulonglong2*)&hsm[k * 64 + (bq ^ fs)];
        ffma2(acc0, w2, hv.x);
        ffma2(acc1, w2, hv.y);
    }
    float2 r0 = lo_hi(acc0), r1 = lo_hi(acc1);
    gsm[nl * 64 + bq + 0] = r0.x + gp[0];
    gsm[nl * 64 + bq + 1] = r0.y + gp[1];
    gsm[nl * 64 + bq + 2] = r1.x + gp[2];
    gsm[nl * 64 + bq + 3] = r1.y + gp[3];
    __syncthreads();

    int bl = tid & 63, hl = tid >> 6;
    float iv = gsm[(0 * 4 + hl) * 64 + bl];
    float fv = gsm[(1 * 4 + hl) * 64 + bl];
    float gv = gsm[(2 * 4 + hl) * 64 + bl];
    float ov = gsm[(3 * 4 + hl) * 64 + bl];
    int b   = bi * 64 + bl;
    int huo = j * 4 + hl;
    float c  = g_cstate[b * 256 + huo];
    float si = 1.f / (1.f + expf(-iv));
    float sf = 1.f / (1.f + expf(-fv));
    float so = 1.f / (1.f + expf(-ov));
    float c2 = sf * c + si * tanhf(gv);
    float h2 = so * tanhf(c2);
    g_cstate[b * 256 + huo] = c2;
    g_hbuf[par ^ 1][b * 256 + huo] = h2;
    __nv_bfloat16 hhi = __float2bfloat16(h2);
    size_t hidx = (size_t)(b * 32 + t) * 256 + huo;
    g_Hhi[hidx] = hhi;
    g_Hlo[hidx] = __float2bfloat16(h2 - __bfloat162float(hhi));
    if (hfinal) hfinal[b * 256 + huo] = h2;
}

// ---------------- launch ----------------
#define GEMM_SMEM 65536

extern "C" void kernel_launch(void* const* d_in, const int* in_sizes, int n_in,
                              void* d_out, int out_size) {
    (void)in_sizes; (void)n_in; (void)out_size;
    const float* enc  = (const float*)d_in[0];
    const float* ench = (const float*)d_in[1];
    const float* encc = (const float*)d_in[2];
    const int*   tgt  = (const int*)  d_in[3];
    const float* emb  = (const float*)d_in[4];
    const float* Uat  = (const float*)d_in[6];
    const float* Vat  = (const float*)d_in[7];
    const float* Wih  = (const float*)d_in[8];
    const float* Whh  = (const float*)d_in[9];
    const float* bih  = (const float*)d_in[10];
    const float* bhh  = (const float*)d_in[11];
    const float* Wout = (const float*)d_in[12];
    const float* bout = (const float*)d_in[13];
    float* out      = (float*)d_out;
    float* out_h    = out + (size_t)128 * 32 * 16000;   // 65,536,000
    float* out_attn = out_h + 128 * 256;                // +32,768

    cudaFuncSetAttribute(k_step, cudaFuncAttributeMaxDynamicSharedMemorySize, STEP_SMEM_BYTES);
    cudaFuncSetAttribute(gemm_mma<0>, cudaFuncAttributeMaxDynamicSharedMemorySize, GEMM_SMEM);
    cudaFuncSetAttribute(gemm_mma<1>, cudaFuncAttributeMaxDynamicSharedMemorySize, GEMM_SMEM);

    k_init<<<128, 256>>>(ench, encc);
    k_prep<<<5, 256>>>(Vat, Uat, bih, bhh);
    k_cvt<<<4000, 256>>>(Wout, 1);
    k_cvt<<<512, 256>>>(Wih, 0);
    k_embed<<<4096, 64>>>(tgt, emb);
    k_attn<<<128, 256>>>(enc, out_attn);
    k_ctx<<<128, 256>>>(enc);
    gemm_mma<0><<<dim3(8, 32), 256, GEMM_SMEM>>>(nullptr, nullptr);
    for (int t = 0; t < 32; t++)
        k_step<<<128, 256, STEP_SMEM_BYTES>>>(Whh, t, t & 1, (t == 31) ? out_h : nullptr);
    gemm_mma<1><<<dim3(125, 32), 256, GEMM_SMEM>>>(bout, out);
}

// round 17
// speedup vs baseline: 1.7747x; 1.0591x over previous
#include <cuda_runtime.h>
#include <cuda_bf16.h>
#include <cstdint>

typedef unsigned long long ull;

// Problem sizes: B=128, S=64, H=256, E=256, V=16000, T=32, START=1
// Output: decoder_outputs [128,32,16000] ++ h [1,128,256] ++ attentions [128,32,64]

// ---------------- device scratch (no mallocs allowed) ----------------
__device__ __align__(16) float g_u[256];            // u[h] = sum_g V[g]*U[g,h]
__device__ __align__(16) float g_bsum[1024];        // b_ih + b_hh
__device__ __align__(16) float g_w[128 * 64];       // attention weights (step-invariant)
__device__ __align__(16) float g_gpre[4096 * 1024]; // X @ W_ih.T + bsum
__device__ __align__(16) float g_hbuf[2][128 * 256];
__device__ __align__(16) float g_cstate[128 * 256];
__device__ __align__(16) __nv_bfloat16 g_Xhi[4096 * 512];   // split-bf16 [emb_relu | ctx]
__device__ __align__(16) __nv_bfloat16 g_Xlo[4096 * 512];
__device__ __align__(16) __nv_bfloat16 g_WihHi[1024 * 512]; // split-bf16 W_ih
__device__ __align__(16) __nv_bfloat16 g_WihLo[1024 * 512];
__device__ __align__(16) __nv_bfloat16 g_Hhi[4096 * 256];   // split-bf16 hidden states
__device__ __align__(16) __nv_bfloat16 g_Hlo[4096 * 256];
__device__ __align__(16) __nv_bfloat16 g_Whi[16000 * 256];  // split-bf16 W_out
__device__ __align__(16) __nv_bfloat16 g_Wlo[16000 * 256];
__device__ int g_barCnt[2];                          // persistent-step group barriers
__device__ int g_barFlag[2];                         // parity flags (toggle 32x -> replay-safe)

// ---------------- f32x2 helpers (PTX-only packed FMA, for LSTM step) ----------------
__device__ __forceinline__ void ffma2(ull &c, ull a, ull b) {
    asm("fma.rn.f32x2 %0, %1, %2, %0;" : "+l"(c) : "l"(a), "l"(b));
}
__device__ __forceinline__ float2 lo_hi(ull v) {
    float2 r; asm("mov.b64 {%0, %1}, %2;" : "=f"(r.x), "=f"(r.y) : "l"(v)); return r;
}

// ---------------- mma.sync / cp.async helpers (family-level PTX) ----------------
__device__ __forceinline__ uint32_t smem_u32(const void* p) {
    uint32_t a;
    asm("{ .reg .u64 t; cvta.to.shared.u64 t, %1; cvt.u32.u64 %0, t; }" : "=r"(a) : "l"(p));
    return a;
}
__device__ __forceinline__ void ldsm4(uint32_t* r, uint32_t addr) {
    asm volatile("ldmatrix.sync.aligned.m8n8.x4.shared.b16 {%0,%1,%2,%3}, [%4];"
        : "=r"(r[0]), "=r"(r[1]), "=r"(r[2]), "=r"(r[3]) : "r"(addr));
}
__device__ __forceinline__ void mma16816(float* c, const uint32_t* a, const uint32_t* b) {
    asm volatile("mma.sync.aligned.m16n8k16.row.col.f32.bf16.bf16.f32 "
        "{%0,%1,%2,%3}, {%4,%5,%6,%7}, {%8,%9}, {%0,%1,%2,%3};"
        : "+f"(c[0]), "+f"(c[1]), "+f"(c[2]), "+f"(c[3])
        : "r"(a[0]), "r"(a[1]), "r"(a[2]), "r"(a[3]), "r"(b[0]), "r"(b[1]));
}
__device__ __forceinline__ void cp16(uint32_t dst, const void* src) {
    asm volatile("cp.async.ca.shared.global [%0], [%1], 16;" :: "r"(dst), "l"(src));
}
#define CP_COMMIT() asm volatile("cp.async.commit_group;" ::: "memory")
#define CP_WAIT0()  asm volatile("cp.async.wait_group 0;" ::: "memory")
#define SWZ(x) ((x) ^ (((x) >> 3) & 0x70))

__device__ __forceinline__ uint32_t pack2bf(float a, float b) {
    __nv_bfloat16 ha = __float2bfloat16(a), hb = __float2bfloat16(b);
    return ((uint32_t)__bfloat16_as_ushort(hb) << 16) | __bfloat16_as_ushort(ha);
}

// ---------------- init: copy initial h / c ----------------
__global__ void k_init(const float* __restrict__ eh, const float* __restrict__ ec) {
    int i = blockIdx.x * 256 + threadIdx.x;
    g_hbuf[0][i] = eh[i];
    g_cstate[i]  = ec[i];
}

// ---------------- prep: u = V @ U_attn ; bsum = b_ih + b_hh ----------------
__global__ void k_prep(const float* __restrict__ Vat, const float* __restrict__ Uat,
                       const float* __restrict__ bih, const float* __restrict__ bhh) {
    int tid = threadIdx.x;
    if (blockIdx.x == 0) {
        float a = 0.f;
        for (int g = 0; g < 256; g++) a += Vat[g] * Uat[g * 256 + tid];
        g_u[tid] = a;
    } else {
        int nn = (blockIdx.x - 1) * 256 + tid;
        g_bsum[nn] = bih[nn] + bhh[nn];
    }
}

// ---------------- split conversion (vectorized float4): mode 0 = W_ih, 1 = W_out ----
__global__ void k_cvt(const float* __restrict__ W, int mode) {
    size_t i = ((size_t)blockIdx.x * 256 + threadIdx.x) * 4;
    float4 w = *(const float4*)(W + i);
    __nv_bfloat16 h0 = __float2bfloat16(w.x), h1 = __float2bfloat16(w.y);
    __nv_bfloat16 h2 = __float2bfloat16(w.z), h3 = __float2bfloat16(w.w);
    uint2 hp;
    hp.x = ((uint32_t)__bfloat16_as_ushort(h1) << 16) | __bfloat16_as_ushort(h0);
    hp.y = ((uint32_t)__bfloat16_as_ushort(h3) << 16) | __bfloat16_as_ushort(h2);
    uint2 lp;
    lp.x = pack2bf(w.x - __bfloat162float(h0), w.y - __bfloat162float(h1));
    lp.y = pack2bf(w.z - __bfloat162float(h2), w.w - __bfloat162float(h3));
    __nv_bfloat16* hi = mode ? g_Whi : g_WihHi;
    __nv_bfloat16* lo = mode ? g_Wlo : g_WihLo;
    *(uint2*)(hi + i) = hp;
    *(uint2*)(lo + i) = lp;
}

// ---------------- embedding gather + relu -> split X[:, 0:256] (float4) ----------------
__global__ void k_embed(const int* __restrict__ tgt, const float* __restrict__ emb) {
    int r = blockIdx.x;           // t*128 + b, grid 4096, 64 threads
    int t = r >> 7, b = r & 127;
    int tok = (t == 0) ? 1 : tgt[b * 32 + (t - 1)];
    float4 v = ((const float4*)(emb + (size_t)tok * 256))[threadIdx.x];
    v.x = fmaxf(v.x, 0.f); v.y = fmaxf(v.y, 0.f);
    v.z = fmaxf(v.z, 0.f); v.w = fmaxf(v.w, 0.f);
    __nv_bfloat16 h0 = __float2bfloat16(v.x), h1 = __float2bfloat16(v.y);
    __nv_bfloat16 h2 = __float2bfloat16(v.z), h3 = __float2bfloat16(v.w);
    uint2 hp;
    hp.x = ((uint32_t)__bfloat16_as_ushort(h1) << 16) | __bfloat16_as_ushort(h0);
    hp.y = ((uint32_t)__bfloat16_as_ushort(h3) << 16) | __bfloat16_as_ushort(h2);
    uint2 lp;
    lp.x = pack2bf(v.x - __bfloat162float(h0), v.y - __bfloat162float(h1));
    lp.y = pack2bf(v.z - __bfloat162float(h2), v.w - __bfloat162float(h3));
    size_t base = (size_t)r * 512 + threadIdx.x * 4;
    *(uint2*)(g_Xhi + base) = hp;
    *(uint2*)(g_Xlo + base) = lp;
}

// ---------------- attention scores + softmax (step-invariant), 256 threads ----------
__global__ void k_attn(const float* __restrict__ enc, float* __restrict__ out_attn) {
    __shared__ float usm[256];
    __shared__ float part[256];
    __shared__ float sc[64];
    int b = blockIdx.x, tid = threadIdx.x;
    int s = tid & 63, q = tid >> 6;
    usm[tid] = g_u[tid];
    __syncthreads();
    const float4* row = (const float4*)(enc + ((size_t)b * 64 + s) * 256 + q * 64);
    float acc = 0.f;
    #pragma unroll
    for (int k = 0; k < 16; k++) {
        float4 e = row[k];
        int u = q * 64 + k * 4;
        acc += e.x * usm[u] + e.y * usm[u+1] + e.z * usm[u+2] + e.w * usm[u+3];
    }
    part[q * 64 + s] = acc;
    __syncthreads();
    if (tid < 64) sc[s] = part[s] + part[64 + s] + part[128 + s] + part[192 + s];
    __syncthreads();
    if (tid < 64) {
        float m = sc[0];
        #pragma unroll 8
        for (int i = 1; i < 64; i++) m = fmaxf(m, sc[i]);
        part[s] = expf(sc[s] - m);
    }
    __syncthreads();
    if (tid < 64) {
        float sum = 0.f;
        #pragma unroll 8
        for (int i = 0; i < 64; i++) sum += part[i];
        float w = part[s] / sum;
        sc[s] = w;
        g_w[b * 64 + s] = w;
    }
    __syncthreads();
    float w = sc[s];
    #pragma unroll
    for (int t0 = 0; t0 < 8; t0++)
        out_attn[(size_t)b * 2048 + (q * 8 + t0) * 64 + s] = w;
}

// ---------------- context = w @ enc ; broadcast -> split X[:, 256:512] ----------------
__global__ void k_ctx(const float* __restrict__ enc) {
    __shared__ float wsh[64];
    int b = blockIdx.x, h = threadIdx.x;    // 128 blocks x 256 threads
    if (h < 64) wsh[h] = g_w[b * 64 + h];
    __syncthreads();
    float acc = 0.f;
    #pragma unroll 8
    for (int s = 0; s < 64; s++) acc += wsh[s] * enc[((size_t)b * 64 + s) * 256 + h];
    __nv_bfloat16 hi = __float2bfloat16(acc);
    __nv_bfloat16 lo = __float2bfloat16(acc - __bfloat162float(hi));
    #pragma unroll
    for (int t = 0; t < 32; t++) {
        size_t idx = (size_t)(t * 128 + b) * 512 + 256 + h;
        g_Xhi[idx] = hi;
        g_Xlo[idx] = lo;
    }
}

// ---------------- split-bf16 HMMA GEMM, cp.async 2-stage pipeline (1 sync/stage) ------
// Block 128x128 C-tile, 8 warps (2 row x 4 col), warp tile 64x32.
// K chunked by 32 elems (64B). Stage = 4 tiles x 8KB = 32KB; 2 stages -> 2 CTAs/SM.
// Loop: wait(stage c) -> sync -> issue(stage c+1) -> consume(stage c).
// Refill safety: buffer (c+1)&1 was consumed at iter c-1, before this iter's sync.
__device__ __forceinline__ void pj_issue(uint32_t sbase,
    const char* Ah, const char* Al, const char* Bh, const char* Bl,
    int ldb, int tid)
{
    const char* s4[4] = {Ah, Al, Bh, Bl};
    #pragma unroll
    for (int tgt = 0; tgt < 4; tgt++) {
        #pragma unroll
        for (int i = 0; i < 2; i++) {
            int u = tid + i * 256;          // 0..511 16B-units
            int r = u >> 2, c16 = u & 3;
            uint32_t pb = (uint32_t)((r >> 1) * 128 + (r & 1) * 64 + c16 * 16);
            cp16(sbase + tgt * 8192 + SWZ(pb), s4[tgt] + (size_t)r * ldb + c16 * 16);
        }
    }
}

template<int MODE>
__global__ __launch_bounds__(256, 2) void gemm_mma(const float* __restrict__ bias_ext,
                                                   float* __restrict__ Cext) {
    constexpr int KK  = (MODE == 0) ? 512 : 256;
    constexpr int LDC = (MODE == 0) ? 1024 : 16000;
    constexpr int NCH = KK / 32;
    const __nv_bfloat16* Ahi = (MODE == 0) ? g_Xhi   : g_Hhi;
    const __nv_bfloat16* Alo = (MODE == 0) ? g_Xlo   : g_Hlo;
    const __nv_bfloat16* Bhi = (MODE == 0) ? g_WihHi : g_Whi;
    const __nv_bfloat16* Blo = (MODE == 0) ? g_WihLo : g_Wlo;
    const float* bias = (MODE == 0) ? g_bsum : bias_ext;
    float*       C    = (MODE == 0) ? g_gpre : Cext;

    extern __shared__ char ts[];
    uint32_t sb = smem_u32(ts);
    int tid = threadIdx.x, lane = tid & 31, wid = tid >> 5;
    int m0 = blockIdx.y * 128, n0 = blockIdx.x * 128;
    int wm = (wid & 1) * 64, wn = (wid >> 1) * 32;

    const char* Ah = (const char*)(Ahi + (size_t)m0 * KK);
    const char* Al = (const char*)(Alo + (size_t)m0 * KK);
    const char* Bh = (const char*)(Bhi + (size_t)n0 * KK);
    const char* Bl = (const char*)(Blo + (size_t)n0 * KK);

    uint32_t aswz[4], bswz[2];
    {
        int al = lane & 15, ah = ((lane >> 4) & 1) * 16;
        #pragma unroll
        for (int fr = 0; fr < 4; fr++) {
            int r = wm + fr * 16 + al;
            aswz[fr] = SWZ((uint32_t)((r >> 1) * 128 + (r & 1) * 64 + ah));
        }
        int nl = (lane & 7) + ((lane >> 4) & 1) * 8;
        int kh = ((lane >> 3) & 1) * 16;
        #pragma unroll
        for (int fb = 0; fb < 2; fb++) {
            int r = wn + fb * 16 + nl;
            bswz[fb] = SWZ((uint32_t)((r >> 1) * 128 + (r & 1) * 64 + kh));
        }
    }

    float acc[4][4][4];
    #pragma unroll
    for (int i = 0; i < 4; i++)
        #pragma unroll
        for (int j = 0; j < 4; j++)
            #pragma unroll
            for (int q = 0; q < 4; q++) acc[i][j][q] = 0.f;

    pj_issue(sb, Ah, Al, Bh, Bl, KK * 2, tid);
    CP_COMMIT();

    #pragma unroll 1
    for (int c = 0; c < NCH; c++) {
        CP_WAIT0();
        __syncthreads();
        if (c + 1 < NCH) {
            int coff = (c + 1) * 64;             // byte offset along K
            pj_issue(sb + ((c + 1) & 1) * 32768,
                     Ah + coff, Al + coff, Bh + coff, Bl + coff, KK * 2, tid);
            CP_COMMIT();
        }
        uint32_t bb = sb + (c & 1) * 32768;
        #pragma unroll
        for (int ks = 0; ks < 2; ks++) {
            uint32_t kx = (uint32_t)(ks << 5);
            uint32_t bh[8], bl[8];
            ldsm4(bh + 0, bb + 16384 + (bswz[0] ^ kx));
            ldsm4(bh + 4, bb + 16384 + (bswz[1] ^ kx));
            ldsm4(bl + 0, bb + 24576 + (bswz[0] ^ kx));
            ldsm4(bl + 4, bb + 24576 + (bswz[1] ^ kx));
            #pragma unroll
            for (int fr = 0; fr < 4; fr++) {
                uint32_t a[4], a2[4];
                ldsm4(a, bb + (aswz[fr] ^ kx));                 // A_hi
                #pragma unroll
                for (int fc = 0; fc < 4; fc++) mma16816(acc[fr][fc], a, bh + fc * 2);
                #pragma unroll
                for (int fc = 0; fc < 4; fc++) mma16816(acc[fr][fc], a, bl + fc * 2);
                ldsm4(a2, bb + 8192 + (aswz[fr] ^ kx));         // A_lo
                #pragma unroll
                for (int fc = 0; fc < 4; fc++) mma16816(acc[fr][fc], a2, bh + fc * 2);
            }
        }
    }

    // epilogue: c0,c1 -> (row, col..col+1); c2,c3 -> (row+8, ...)
    int r0 = m0 + wm + (lane >> 2);
    int cb = n0 + wn + (lane & 3) * 2;
    #pragma unroll
    for (int fr = 0; fr < 4; fr++) {
        #pragma unroll
        for (int fc = 0; fc < 4; fc++) {
            int row = r0 + fr * 16;
            int col = cb + fc * 8;
            float2 b2 = *(const float2*)&bias[col];
            float2 o0 = make_float2(acc[fr][fc][0] + b2.x, acc[fr][fc][1] + b2.y);
            float2 o1 = make_float2(acc[fr][fc][2] + b2.x, acc[fr][fc][3] + b2.y);
            *(float2*)&C[(size_t)row * LDC + col]       = o0;
            *(float2*)&C[(size_t)(row + 8) * LDC + col] = o1;
        }
    }
}

// ---------------- persistent recurrent loop: 32 LSTM steps in ONE kernel ----------------
// grid 128 = (bi 0..1) x (j 0..63), 256 threads, <=2 CTAs/SM by smem -> all resident.
// Cross-block dependency per step exists only among the 64 blocks sharing bi ->
// two independent 64-block parity barriers; 32 toggles return flags to 0 (replay-safe).
#define STEP_SMEM_FLOATS (256*64 + 256*17*2 + 16*64)
#define STEP_SMEM_BYTES  (STEP_SMEM_FLOATS * 4)

__global__ __launch_bounds__(256) void k_step_all(const float* __restrict__ Whh,
                                                  float* __restrict__ hfinal) {
    extern __shared__ __align__(16) float sm[];
    float*  hsm  = sm;                              // [k 256][b 64], XOR-swizzled
    float2* Wsm2 = (float2*)(sm + 256 * 64);        // [k 256][row 16] dup pairs, stride 17
    float*  gsm  = sm + 256 * 64 + 256 * 17 * 2;    // [16][64]

    int tid = threadIdx.x;
    int j  = blockIdx.x & 63;
    int bi = blockIdx.x >> 6;

    // W_hh tile: load ONCE (constant across steps)
    #pragma unroll
    for (int i = 0; i < 16; i++) {
        int idx = tid + i * 256;
        int row = idx >> 8;
        int k   = idx & 255;
        int hu   = j * 4 + (row & 3);
        int gate = row >> 2;
        float wv = Whh[(gate * 256 + hu) * 256 + k];
        Wsm2[k * 17 + row] = make_float2(wv, wv);
    }

    int lane = tid & 31, warp = tid >> 5;
    int nl = lane & 15;
    int bq = warp * 8 + (lane >> 4) * 4;
    int hu = j * 4 + (nl & 3);
    int n  = (nl >> 2) * 256 + hu;
    int bl = tid & 63, hl = tid >> 6;
    int b   = bi * 64 + bl;
    int huo = j * 4 + hl;

    #pragma unroll 1
    for (int t = 0; t < 32; t++) {
        int par = t & 1;
        const float* hprev = g_hbuf[par] + bi * 64 * 256;

        // load h transposed, coalesced LDG.128 + swizzled STS
        #pragma unroll
        for (int i = 0; i < 16; i++) {
            int idx = tid + i * 256;
            int rb = idx >> 6;
            int kq = (idx & 63) << 2;
            float4 v = *(const float4*)&hprev[rb * 256 + kq];
            float vv[4] = {v.x, v.y, v.z, v.w};
            #pragma unroll
            for (int d = 0; d < 4; d++) {
                int k = kq + d;
                int fs = ((k >> 2) & 7) << 2;
                hsm[k * 64 + (rb ^ fs)] = vv[d];
            }
        }
        float gp[4];
        #pragma unroll
        for (int i2 = 0; i2 < 4; i2++)
            gp[i2] = g_gpre[(size_t)(t * 128 + bi * 64 + bq + i2) * 1024 + n];

        __syncthreads();

        ull acc0 = 0ull, acc1 = 0ull;
        #pragma unroll 8
        for (int k = 0; k < 256; k++) {
            int fs = ((k >> 2) & 7) << 2;
            ull w2 = *(const ull*)&Wsm2[k * 17 + nl];
            ulonglong2 hv = *(const ulonglong2*)&hsm[k * 64 + (bq ^ fs)];
            ffma2(acc0, w2, hv.x);
            ffma2(acc1, w2, hv.y);
        }
        float2 r0 = lo_hi(acc0), r1 = lo_hi(acc1);
        gsm[nl * 64 + bq + 0] = r0.x + gp[0];
        gsm[nl * 64 + bq + 1] = r0.y + gp[1];
        gsm[nl * 64 + bq + 2] = r1.x + gp[2];
        gsm[nl * 64 + bq + 3] = r1.y + gp[3];
        __syncthreads();

        float iv = gsm[(0 * 4 + hl) * 64 + bl];
        float fv = gsm[(1 * 4 + hl) * 64 + bl];
        float gv = gsm[(2 * 4 + hl) * 64 + bl];
        float ov = gsm[(3 * 4 + hl) * 64 + bl];
        float c  = g_cstate[b * 256 + huo];
        float si = 1.f / (1.f + expf(-iv));
        float sf = 1.f / (1.f + expf(-fv));
        float so = 1.f / (1.f + expf(-ov));
        float c2 = sf * c + si * tanhf(gv);
        float h2 = so * tanhf(c2);
        g_cstate[b * 256 + huo] = c2;
        g_hbuf[par ^ 1][b * 256 + huo] = h2;
        __nv_bfloat16 hhi = __float2bfloat16(h2);
        size_t hidx = (size_t)(b * 32 + t) * 256 + huo;
        g_Hhi[hidx] = hhi;
        g_Hlo[hidx] = __float2bfloat16(h2 - __bfloat162float(hhi));
        if (t == 31) hfinal[b * 256 + huo] = h2;

        // group barrier: 64 blocks sharing bi (parity flag toggles 0->1->0..., 32x -> ends 0)
        __threadfence();
        __syncthreads();
        if (tid == 0) {
            int want = (t & 1) ^ 1;
            int prev = atomicAdd(&g_barCnt[bi], 1);
            if (prev == 63) {
                atomicExch(&g_barCnt[bi], 0);
                __threadfence();
                atomicExch(&g_barFlag[bi], want);
            } else {
                while (atomicAdd(&g_barFlag[bi], 0) != want) { }
            }
        }
        __syncthreads();
        __threadfence();
    }
}

// ---------------- launch ----------------
#define GEMM_SMEM 65536

extern "C" void kernel_launch(void* const* d_in, const int* in_sizes, int n_in,
                              void* d_out, int out_size) {
    (void)in_sizes; (void)n_in; (void)out_size;
    const float* enc  = (const float*)d_in[0];
    const float* ench = (const float*)d_in[1];
    const float* encc = (const float*)d_in[2];
    const int*   tgt  = (const int*)  d_in[3];
    const float* emb  = (const float*)d_in[4];
    const float* Uat  = (const float*)d_in[6];
    const float* Vat  = (const float*)d_in[7];
    const float* Wih  = (const float*)d_in[8];
    const float* Whh  = (const float*)d_in[9];
    const float* bih  = (const float*)d_in[10];
    const float* bhh  = (const float*)d_in[11];
    const float* Wout = (const float*)d_in[12];
    const float* bout = (const float*)d_in[13];
    float* out      = (float*)d_out;
    float* out_h    = out + (size_t)128 * 32 * 16000;   // 65,536,000
    float* out_attn = out_h + 128 * 256;                // +32,768

    cudaFuncSetAttribute(k_step_all, cudaFuncAttributeMaxDynamicSharedMemorySize, STEP_SMEM_BYTES);
    cudaFuncSetAttribute(gemm_mma<0>, cudaFuncAttributeMaxDynamicSharedMemorySize, GEMM_SMEM);
    cudaFuncSetAttribute(gemm_mma<1>, cudaFuncAttributeMaxDynamicSharedMemorySize, GEMM_SMEM);

    k_init<<<128, 256>>>(ench, encc);                       // launch 1
    k_prep<<<5, 256>>>(Vat, Uat, bih, bhh);                 // launch 2
    k_cvt<<<4000, 256>>>(Wout, 1);                          // launch 3
    // launch 4: DIAGNOSTIC one-wave projection (ncu captures launch #4).
    // Reads stale g_H (deterministic final output: real projection overwrites below).
    gemm_mma<1><<<dim3(125, 1), 256, GEMM_SMEM>>>(bout, out);
    k_cvt<<<512, 256>>>(Wih, 0);                            // launch 5
    k_embed<<<4096, 64>>>(tgt, emb);                        // launch 6
    k_attn<<<128, 256>>>(enc, out_attn);                    // launch 7
    k_ctx<<<128, 256>>>(enc);                               // launch 8
    gemm_mma<0><<<dim3(8, 32), 256, GEMM_SMEM>>>(nullptr, nullptr);   // launch 9
    k_step_all<<<128, 256, STEP_SMEM_BYTES>>>(Whh, out_h);  // launch 10 (replaces 32)
    gemm_mma<1><<<dim3(125, 32), 256, GEMM_SMEM>>>(bout, out);        // launch 11
}